// round 1
// baseline (speedup 1.0000x reference)
#include <cuda_runtime.h>

// Laplacian_22711787061657
// x: (32, 1, 1024, 1024) fp32. Circular 2nd difference along H and W:
//   gx[h][w] = x[h-2][w] - 2*x[h-1][w] + x[h][w]   (indices mod 1024)
//   gy[h][w] = x[h][w-2] - 2*x[h][w-1] + x[h][w]   (indices mod 1024)
//   out = clip(gx+gy, -1, 1) * 0.5, NaN(x)->1.0 on input, NaN->0 on output.
//
// Memory-bound design: each thread owns one float4 column group, walks 64
// consecutive rows keeping rows h-1/h-2 in rolling registers (no H read
// amplification), and fetches one extra aligned float4 (w-4) per row for the
// W-shifted lanes (L1 hit: it's the neighbor thread's current load).

#define HW 1024           // H == W == 1024
#define ROW_F4 (HW / 4)   // 256 float4 per row
#define CHUNK 64          // rows per block
#define NCHUNK (HW / CHUNK)

__device__ __forceinline__ float4 scrub1(float4 v) {
    // remove_nan(x, 1.0)
    v.x = isnan(v.x) ? 1.0f : v.x;
    v.y = isnan(v.y) ? 1.0f : v.y;
    v.z = isnan(v.z) ? 1.0f : v.z;
    v.w = isnan(v.w) ? 1.0f : v.w;
    return v;
}

__device__ __forceinline__ float finish(float g) {
    // clip(g, -1, 1) * 0.5, then NaN -> 0
    g = fminf(1.0f, fmaxf(-1.0f, g));
    g *= 0.5f;
    return isnan(g) ? 0.0f : g;
}

__global__ __launch_bounds__(ROW_F4, 4)
void laplacian_kernel(const float4* __restrict__ x, float4* __restrict__ out) {
    const int t     = threadIdx.x;        // column float4 index, 0..255
    const int chunk = blockIdx.x;         // 0..NCHUNK-1
    const int b     = blockIdx.y;         // image index

    const size_t img_off = (size_t)b * (HW * ROW_F4);
    const float4* __restrict__ xi = x + img_off;
    float4* __restrict__ oi = out + img_off;

    const int tp = (t + ROW_F4 - 1) & (ROW_F4 - 1); // float4 at w-4 (circular)

    const int h0 = chunk * CHUNK;
    // preload rows h0-2, h0-1 (circular)
    const int hm2 = (h0 + HW - 2) & (HW - 1);
    const int hm1 = (h0 + HW - 1) & (HW - 1);

    float4 rm2 = scrub1(xi[(size_t)hm2 * ROW_F4 + t]); // row h-2
    float4 rm1 = scrub1(xi[(size_t)hm1 * ROW_F4 + t]); // row h-1

    #pragma unroll 4
    for (int h = h0; h < h0 + CHUNK; ++h) {
        const float4 a = scrub1(xi[(size_t)h * ROW_F4 + t]);   // row h, w..w+3
        const float4 p = scrub1(xi[(size_t)h * ROW_F4 + tp]);  // row h, w-4..w-1

        // gx = rm2 - 2*rm1 + a (per lane)
        // gy lanes: [p.z-2p.w+a.x, p.w-2a.x+a.y, a.x-2a.y+a.z, a.y-2a.z+a.w]
        float4 g;
        g.x = (rm2.x - 2.0f * rm1.x + a.x) + (p.z - 2.0f * p.w + a.x);
        g.y = (rm2.y - 2.0f * rm1.y + a.y) + (p.w - 2.0f * a.x + a.y);
        g.z = (rm2.z - 2.0f * rm1.z + a.z) + (a.x - 2.0f * a.y + a.z);
        g.w = (rm2.w - 2.0f * rm1.w + a.w) + (a.y - 2.0f * a.z + a.w);

        g.x = finish(g.x);
        g.y = finish(g.y);
        g.z = finish(g.z);
        g.w = finish(g.w);

        oi[(size_t)h * ROW_F4 + t] = g;

        rm2 = rm1;
        rm1 = a;
    }
}

extern "C" void kernel_launch(void* const* d_in, const int* in_sizes, int n_in,
                              void* d_out, int out_size) {
    const float4* x = (const float4*)d_in[0];
    float4* out = (float4*)d_out;
    const int batch = in_sizes[0] / (HW * HW); // 32

    dim3 grid(NCHUNK, batch);
    dim3 block(ROW_F4);
    laplacian_kernel<<<grid, block>>>(x, out);
}